// round 1
// baseline (speedup 1.0000x reference)
#include <cuda_runtime.h>
#include <cuda_bf16.h>

// Problem constants
#define T_STEPS 2048
#define BATCH   512
#define INPUT   42
#define HIDDEN  64
#define GATES   (4 * HIDDEN)   // 256
#define OUT_DIM 2

// Scratch: x_proj for batch row 511 only. (T, 4H) = 2048 x 256 floats = 2 MB.
__device__ float g_xproj[T_STEPS * GATES];

// ---------------------------------------------------------------------------
// Kernel 1: x_proj[t, g] = dot(x[t, 511, :], W_ih[g, :]) + b_ih[g] + b_hh[g]
// One block per timestep, 256 threads (one per gate).
// ---------------------------------------------------------------------------
__global__ void xproj_kernel(const float* __restrict__ x,
                             const float* __restrict__ Wih,
                             const float* __restrict__ bih,
                             const float* __restrict__ bhh)
{
    __shared__ __align__(16) float xs[INPUT];
    const int t = blockIdx.x;
    const int j = threadIdx.x;

    if (j < INPUT) {
        // x index: (t * BATCH + 511) * INPUT + j
        xs[j] = x[((size_t)t * BATCH + (BATCH - 1)) * INPUT + j];
    }
    __syncthreads();

    float acc = bih[j] + bhh[j];
    const float* wr = Wih + j * INPUT;
#pragma unroll
    for (int k = 0; k < INPUT; k++) {
        acc = fmaf(xs[k], __ldg(&wr[k]), acc);
    }
    g_xproj[t * GATES + j] = acc;
}

// ---------------------------------------------------------------------------
// Fast activations (exp-based; rel error ~2^-22, safe at 1e-3 tolerance)
// ---------------------------------------------------------------------------
__device__ __forceinline__ float fast_sigmoid(float x)
{
    return __fdividef(1.0f, 1.0f + __expf(-x));
}

__device__ __forceinline__ float fast_tanh(float x)
{
    // tanh(x) = 1 - 2/(exp(2x)+1); saturates correctly at +/-inf of exp
    return 1.0f - __fdividef(2.0f, __expf(2.0f * x) + 1.0f);
}

// ---------------------------------------------------------------------------
// Kernel 2: sequential LSTM scan over T=2048, single block, 256 threads.
// Thread j owns gate j (j<64: i, <128: f, <192: g, <256: o).
// Threads 0..63 own c[n] in registers and update h.
// Warps 2,3 (threads 64..127) compute the (T,2) output via shuffle reduce.
// ---------------------------------------------------------------------------
__global__ void __launch_bounds__(GATES, 1)
lstm_scan_kernel(const float* __restrict__ Whh,
                 const float* __restrict__ Wout,
                 const float* __restrict__ bout,
                 float* __restrict__ out)
{
    __shared__ __align__(16) float h_sh[HIDDEN];
    __shared__ float gact[GATES];
    __shared__ float wout_sh[OUT_DIM * HIDDEN];

    const int j = threadIdx.x;

    // Register-resident W_hh row for this gate: W_hh[j, 0..63]
    float w[HIDDEN];
#pragma unroll
    for (int k = 0; k < HIDDEN; k++) {
        w[k] = Whh[j * HIDDEN + k];
    }

    if (j < HIDDEN) h_sh[j] = 0.0f;
    if (j < OUT_DIM * HIDDEN) wout_sh[j] = Wout[j];
    float c = 0.0f;                    // valid for j < 64
    const float b0 = bout[0], b1 = bout[1];

    // Prefetch t=0 xproj
    float xp = g_xproj[j];
    __syncthreads();

    for (int t = 0; t < T_STEPS; t++) {
        // Prefetch next step's xproj (hidden behind this step's compute)
        float xp_next = 0.0f;
        if (t + 1 < T_STEPS) xp_next = g_xproj[(t + 1) * GATES + j];

        // Gate pre-activation: xp + dot(h, W_hh[j,:])
        float a0 = 0.f, a1 = 0.f, a2 = 0.f, a3 = 0.f;
#pragma unroll
        for (int k = 0; k < HIDDEN; k += 4) {
            float4 hv = *reinterpret_cast<const float4*>(&h_sh[k]);
            a0 = fmaf(hv.x, w[k + 0], a0);
            a1 = fmaf(hv.y, w[k + 1], a1);
            a2 = fmaf(hv.z, w[k + 2], a2);
            a3 = fmaf(hv.w, w[k + 3], a3);
        }
        float a = xp + ((a0 + a1) + (a2 + a3));

        // Activation: tanh for g-gates (128..191), sigmoid otherwise
        float v;
        if (j >= 2 * HIDDEN && j < 3 * HIDDEN) v = fast_tanh(a);
        else                                    v = fast_sigmoid(a);
        gact[j] = v;
        __syncthreads();

        // Cell + hidden update (threads 0..63)
        if (j < HIDDEN) {
            float gi = gact[j];
            float gf = gact[HIDDEN + j];
            float gg = gact[2 * HIDDEN + j];
            float go = gact[3 * HIDDEN + j];
            c = fmaf(gf, c, gi * gg);
            h_sh[j] = go * fast_tanh(c);
        }
        __syncthreads();

        // Output: out[t, o] = dot(h, W_out[o,:]) + b_out[o]
        // warps 2 & 3 (threads 64..127), one warp per output column
        if (j >= 64 && j < 128) {
            int o = (j - 64) >> 5;
            int l = j & 31;
            float p = h_sh[l] * wout_sh[o * HIDDEN + l]
                    + h_sh[l + 32] * wout_sh[o * HIDDEN + l + 32];
#pragma unroll
            for (int s = 16; s > 0; s >>= 1)
                p += __shfl_xor_sync(0xFFFFFFFF, p, s);
            if (l == 0) out[t * OUT_DIM + o] = p + (o == 0 ? b0 : b1);
        }

        xp = xp_next;
    }
}

// ---------------------------------------------------------------------------
// Launcher
// ---------------------------------------------------------------------------
extern "C" void kernel_launch(void* const* d_in, const int* in_sizes, int n_in,
                              void* d_out, int out_size)
{
    const float* x    = (const float*)d_in[0];  // (T, B, 42)
    const float* Wih  = (const float*)d_in[1];  // (256, 42)
    const float* Whh  = (const float*)d_in[2];  // (256, 64)
    const float* bih  = (const float*)d_in[3];  // (256,)
    const float* bhh  = (const float*)d_in[4];  // (256,)
    const float* Wout = (const float*)d_in[5];  // (2, 64)
    const float* bout = (const float*)d_in[6];  // (2,)
    float* out = (float*)d_out;                 // (T, 2)

    xproj_kernel<<<T_STEPS, GATES>>>(x, Wih, bih, bhh);
    lstm_scan_kernel<<<1, GATES>>>(Whh, Wout, bout, out);
}